// round 1
// baseline (speedup 1.0000x reference)
#include <cuda_runtime.h>

#define N_USER 6144
#define N_ITEM 6144
#define NTOT   12288
#define D      64
#define BATCH  2048
#define NNEG   8192      // 4*BATCH
#define MAXF   2049      // 1 + BATCH
#define MAXU   10240     // BATCH + NNEG
#define ROWS_PER_BLK 4

// -------- scratch (device globals; no allocation allowed) --------
__device__ float g_ego[NTOT * D];          // concat(user_emb, item_emb)
__device__ float g_egoF[MAXF * D];         // compacted ego rows at flagged indices
__device__ float g_prop[NTOT * D];         // A_hat @ ego, only at needed rows
__device__ int   g_flag[NTOT];
__device__ int   g_needed[NTOT];
__device__ int   g_listF[MAXF];
__device__ int   g_listU[MAXU];
__device__ int   g_cF, g_cU;

// -------- 1. init: build ego concat, zero bitmaps --------
__global__ void k_init(const float* __restrict__ ue, const float* __restrict__ ie) {
    int r = blockIdx.x, d = threadIdx.x;
    g_ego[r * D + d] = (r < N_USER) ? ue[r * D + d] : ie[(r - N_USER) * D + d];
    if (d == 0) { g_flag[r] = 0; g_needed[r] = 0; }
}

// -------- 2. scatter flags / needed --------
__global__ void k_scatter(const int* __restrict__ users,
                          const int* __restrict__ pos,
                          const int* __restrict__ neg) {
    int t = blockIdx.x * blockDim.x + threadIdx.x;
    if (t == 0) { g_flag[users[0]] = 1; }               // users[:1]
    if (t < BATCH) {
        int rp = N_USER + pos[t];
        g_flag[rp] = 1; g_needed[rp] = 1;               // pos rows: flagged + queried
        g_needed[users[t]] = 1;                          // user rows: queried
    }
    if (t < NNEG) g_needed[N_USER + neg[t]] = 1;         // neg rows: queried
}

// -------- 3. deterministic compaction (single block, ascending order) --------
__global__ void k_compact() {
    __shared__ int warpF[32], warpU[32];
    __shared__ int baseF, baseU;
    int tid = threadIdx.x, lane = tid & 31, wid = tid >> 5;
    if (tid == 0) { baseF = 0; baseU = 0; }
    __syncthreads();
    for (int base = 0; base < NTOT; base += 1024) {
        int i = base + tid;
        int f = g_flag[i];
        int u = (!f) && g_needed[i];
        unsigned bf = __ballot_sync(0xFFFFFFFFu, f);
        unsigned bu = __ballot_sync(0xFFFFFFFFu, u);
        if (lane == 0) { warpF[wid] = __popc(bf); warpU[wid] = __popc(bu); }
        __syncthreads();
        int offF = baseF, offU = baseU;
        for (int k = 0; k < wid; ++k) { offF += warpF[k]; offU += warpU[k]; }
        if (f) g_listF[offF + __popc(bf & ((1u << lane) - 1u))] = i;
        if (u) g_listU[offU + __popc(bu & ((1u << lane) - 1u))] = i;
        __syncthreads();
        if (tid == 0) {
            for (int k = 0; k < 32; ++k) { baseF += warpF[k]; baseU += warpU[k]; }
        }
        __syncthreads();
    }
    if (tid == 0) { g_cF = baseF; g_cU = baseU; }
}

// -------- 4. compact ego at flagged columns --------
__global__ void k_egoF() {
    int j = blockIdx.x, d = threadIdx.x;
    if (j < g_cF) g_egoF[j * D + d] = g_ego[(size_t)g_listF[j] * D + d];
}

// -------- 5. Pass A: flagged rows, full dot with ego --------
// 4 rows/block, 256 threads = 8 warps; each warp owns a contiguous 1536-col stripe;
// each lane holds float2 over D.
__global__ void __launch_bounds__(256) k_passA(const float* __restrict__ adj) {
    int nF = g_cF;
    int jb = blockIdx.x * ROWS_PER_BLK;
    if (jb >= nF) return;
    int tid = threadIdx.x, w = tid >> 5, lane = tid & 31;

    const float* arow[ROWS_PER_BLK];
#pragma unroll
    for (int k = 0; k < ROWS_PER_BLK; ++k) {
        int r = (jb + k < nF) ? g_listF[jb + k] : g_listF[jb];
        arow[k] = adj + (size_t)r * NTOT;
    }

    float2 a0 = {0.f,0.f}, a1 = {0.f,0.f}, a2 = {0.f,0.f}, a3 = {0.f,0.f};
    int c0 = w * (NTOT / 8), c1 = c0 + (NTOT / 8);
    const float* egobase = g_ego + lane * 2;

#pragma unroll 4
    for (int c = c0; c < c1; ++c) {
        float2 e = *(const float2*)(egobase + c * D);
        float w0 = arow[0][c], w1 = arow[1][c], w2 = arow[2][c], w3 = arow[3][c];
        a0.x += w0 * e.x; a0.y += w0 * e.y;
        a1.x += w1 * e.x; a1.y += w1 * e.y;
        a2.x += w2 * e.x; a2.y += w2 * e.y;
        a3.x += w3 * e.x; a3.y += w3 * e.y;
    }

    __shared__ float s[8][ROWS_PER_BLK][D];
    s[w][0][lane*2] = a0.x; s[w][0][lane*2+1] = a0.y;
    s[w][1][lane*2] = a1.x; s[w][1][lane*2+1] = a1.y;
    s[w][2][lane*2] = a2.x; s[w][2][lane*2+1] = a2.y;
    s[w][3][lane*2] = a3.x; s[w][3][lane*2+1] = a3.y;
    __syncthreads();

    int rq = tid >> 6, d = tid & 63;
    float sum = 0.f;
#pragma unroll
    for (int ww = 0; ww < 8; ++ww) sum += s[ww][rq][d];
    if (jb + rq < nF) g_prop[(size_t)g_listF[jb + rq] * D + d] = sum;
}

// -------- 6. Pass B: unflagged needed rows, dot over flagged columns only --------
__global__ void __launch_bounds__(256) k_passB(const float* __restrict__ adj) {
    int nF = g_cF, nU = g_cU;
    int jb = blockIdx.x * ROWS_PER_BLK;
    if (jb >= nU) return;
    int tid = threadIdx.x, w = tid >> 5, lane = tid & 31;

    const float* arow[ROWS_PER_BLK];
#pragma unroll
    for (int k = 0; k < ROWS_PER_BLK; ++k) {
        int r = (jb + k < nU) ? g_listU[jb + k] : g_listU[jb];
        arow[k] = adj + (size_t)r * NTOT;
    }

    float2 a0 = {0.f,0.f}, a1 = {0.f,0.f}, a2 = {0.f,0.f}, a3 = {0.f,0.f};
    int stripe = (nF + 7) >> 3;
    int t0 = w * stripe;
    int t1 = t0 + stripe; if (t1 > nF) t1 = nF;
    const float* egobase = g_egoF + lane * 2;

#pragma unroll 4
    for (int t = t0; t < t1; ++t) {
        int c = g_listF[t];                               // ascending -> streaming-ish
        float2 e = *(const float2*)(egobase + t * D);     // compact, coalesced
        float w0 = arow[0][c], w1 = arow[1][c], w2 = arow[2][c], w3 = arow[3][c];
        a0.x += w0 * e.x; a0.y += w0 * e.y;
        a1.x += w1 * e.x; a1.y += w1 * e.y;
        a2.x += w2 * e.x; a2.y += w2 * e.y;
        a3.x += w3 * e.x; a3.y += w3 * e.y;
    }

    __shared__ float s[8][ROWS_PER_BLK][D];
    s[w][0][lane*2] = a0.x; s[w][0][lane*2+1] = a0.y;
    s[w][1][lane*2] = a1.x; s[w][1][lane*2+1] = a1.y;
    s[w][2][lane*2] = a2.x; s[w][2][lane*2+1] = a2.y;
    s[w][3][lane*2] = a3.x; s[w][3][lane*2+1] = a3.y;
    __syncthreads();

    int rq = tid >> 6, d = tid & 63;
    float sum = 0.f;
#pragma unroll
    for (int ww = 0; ww < 8; ++ww) sum += s[ww][rq][d];
    if (jb + rq < nU) g_prop[(size_t)g_listU[jb + rq] * D + d] = sum;
}

// -------- 7. gather outputs: (ego + 3*prop)/4 at query rows --------
__global__ void k_gather(const int* __restrict__ users,
                         const int* __restrict__ pos,
                         const int* __restrict__ neg,
                         float* __restrict__ out) {
    int q = blockIdx.x, d = threadIdx.x;
    int r;
    if (q < BATCH)            r = users[q];
    else if (q < 2 * BATCH)   r = N_USER + pos[q - BATCH];
    else                      r = N_USER + neg[q - 2 * BATCH];
    size_t o = (size_t)r * D + d;
    out[(size_t)q * D + d] = 0.25f * (g_ego[o] + 3.0f * g_prop[o]);
}

extern "C" void kernel_launch(void* const* d_in, const int* in_sizes, int n_in,
                              void* d_out, int out_size) {
    const float* adj   = (const float*)d_in[0];
    const float* ue    = (const float*)d_in[1];
    const float* ie    = (const float*)d_in[2];
    const int*   users = (const int*)d_in[3];
    const int*   pos   = (const int*)d_in[4];
    const int*   neg   = (const int*)d_in[5];
    float*       out   = (float*)d_out;

    k_init<<<NTOT, D>>>(ue, ie);
    k_scatter<<<(NNEG + 255) / 256, 256>>>(users, pos, neg);
    k_compact<<<1, 1024>>>();
    k_egoF<<<MAXF, D>>>();
    k_passA<<<(MAXF + ROWS_PER_BLK - 1) / ROWS_PER_BLK, 256>>>(adj);
    k_passB<<<(MAXU + ROWS_PER_BLK - 1) / ROWS_PER_BLK, 256>>>(adj);
    k_gather<<<6 * BATCH, D>>>(users, pos, neg, out);
}

// round 2
// speedup vs baseline: 1.2102x; 1.2102x over previous
#include <cuda_runtime.h>

#define N_USER   6144
#define NTOT     12288
#define D        64
#define BATCH    2048
#define NNEG     8192
#define MAXF     2049
#define MAXF_PAD 2080          // multiple of 32, >= MAXF
#define MAXU     10240
#define MT       64            // rows per block tile
#define KT       32            // k per tile
#define SPLITA   12            // 384 k-tiles / 12 = 32 each
#define SPLITB   4
#define TILES_A  ((NTOT / KT) / SPLITA)   // 32

// -------- scratch (device globals; no allocation allowed) --------
__device__ float g_ego[NTOT * D];
__device__ float g_egoF[MAXF_PAD * D];     // compacted ego rows at flagged cols (zero-padded)
__device__ int   g_flag[NTOT];
__device__ int   g_needed[NTOT];
__device__ int   g_listF[MAXF_PAD];
__device__ int   g_listU[MAXU];
__device__ int   g_pos[NTOT];              // row -> compact position (F: j, U: MAXF_PAD+j)
__device__ int   g_cF, g_cU;
__device__ float g_pA[SPLITA][MAXF_PAD * D];   // split-K partials, pass A
__device__ float g_pB[SPLITB][MAXU * D];       // split-K partials, pass B

// -------- 1. init --------
__global__ void k_init(const float* __restrict__ ue, const float* __restrict__ ie) {
    int r = blockIdx.x, d = threadIdx.x;
    g_ego[r * D + d] = (r < N_USER) ? ue[r * D + d] : ie[(r - N_USER) * D + d];
    if (d == 0) { g_flag[r] = 0; g_needed[r] = 0; }
}

// -------- 2. scatter flags / needed --------
__global__ void k_scatter(const int* __restrict__ users,
                          const int* __restrict__ pos,
                          const int* __restrict__ neg) {
    int t = blockIdx.x * blockDim.x + threadIdx.x;
    if (t == 0) g_flag[users[0]] = 1;
    if (t < BATCH) {
        int rp = N_USER + pos[t];
        g_flag[rp] = 1; g_needed[rp] = 1;
        g_needed[users[t]] = 1;
    }
    if (t < NNEG) g_needed[N_USER + neg[t]] = 1;
}

// -------- 3. deterministic compaction (ascending) --------
__global__ void k_compact() {
    __shared__ int warpF[32], warpU[32];
    __shared__ int baseF, baseU;
    int tid = threadIdx.x, lane = tid & 31, wid = tid >> 5;
    if (tid == 0) { baseF = 0; baseU = 0; }
    __syncthreads();
    for (int base = 0; base < NTOT; base += 1024) {
        int i = base + tid;
        int f = g_flag[i];
        int u = (!f) && g_needed[i];
        unsigned bf = __ballot_sync(0xFFFFFFFFu, f);
        unsigned bu = __ballot_sync(0xFFFFFFFFu, u);
        if (lane == 0) { warpF[wid] = __popc(bf); warpU[wid] = __popc(bu); }
        __syncthreads();
        int offF = baseF, offU = baseU;
        for (int k = 0; k < wid; ++k) { offF += warpF[k]; offU += warpU[k]; }
        if (f) g_listF[offF + __popc(bf & ((1u << lane) - 1u))] = i;
        if (u) g_listU[offU + __popc(bu & ((1u << lane) - 1u))] = i;
        __syncthreads();
        if (tid == 0)
            for (int k = 0; k < 32; ++k) { baseF += warpF[k]; baseU += warpU[k]; }
        __syncthreads();
    }
    if (tid == 0) { g_cF = baseF; g_cU = baseU; }
}

// -------- 4. compact ego at flagged cols (zero-padded) + position map --------
__global__ void k_prep() {
    int j = blockIdx.x, d = threadIdx.x;
    int cF = g_cF, cU = g_cU;
    if (j < MAXF_PAD) {
        float v = 0.f;
        if (j < cF) v = g_ego[(size_t)g_listF[j] * D + d];
        g_egoF[j * D + d] = v;
    }
    if (d == 0) {
        if (j < cF) g_pos[g_listF[j]] = j;
        if (j < cU) g_pos[g_listU[j]] = MAXF_PAD + j;
    }
}

// -------- fma micro-tile --------
#define FMA_TILE(accv, av, ev)                                   \
    _Pragma("unroll") for (int _i = 0; _i < 4; ++_i)             \
    _Pragma("unroll") for (int _j = 0; _j < 8; ++_j)             \
        accv[_i][_j] += av[_i] * ev[_j];

// -------- 5. Pass A: flagged rows x full ego (tiled SGEMM, split-K) --------
__global__ void __launch_bounds__(128) k_passA(const float* __restrict__ adj) {
    int nF = g_cF;
    int rb = blockIdx.x * MT;
    if (rb >= nF) return;
    int split = blockIdx.y;
    int kt0 = split * TILES_A;

    __shared__ float sA[MT][KT + 4];
    __shared__ float sE[KT][68];
    __shared__ const float* sRow[MT];

    int tid = threadIdx.x;
    if (tid < MT) {
        int rr = rb + tid; if (rr >= nF) rr = nF - 1;
        sRow[tid] = adj + (size_t)g_listF[rr] * NTOT;
    }
    __syncthreads();

    float acc[4][8];
#pragma unroll
    for (int i = 0; i < 4; ++i)
#pragma unroll
        for (int j = 0; j < 8; ++j) acc[i][j] = 0.f;

    int ty = tid >> 3, tx = tid & 7;
    int r0 = ty * 4, c0 = tx * 8;

    for (int t = 0; t < TILES_A; ++t) {
        int k0 = (kt0 + t) * KT;
        // stage adjacency tile (coalesced float4)
#pragma unroll
        for (int j = 0; j < 4; ++j) {
            int idx = tid + j * 128;
            int row = idx >> 3, seg = idx & 7;
            float4 v = *(const float4*)(sRow[row] + k0 + seg * 4);
            *(float4*)&sA[row][seg * 4] = v;
        }
        // stage ego tile (coalesced float4)
#pragma unroll
        for (int j = 0; j < 4; ++j) {
            int idx = tid + j * 128;
            int k = idx >> 4, dseg = idx & 15;
            float4 v = *(const float4*)(g_ego + (size_t)(k0 + k) * D + dseg * 4);
            *(float4*)&sE[k][dseg * 4] = v;
        }
        __syncthreads();
#pragma unroll 8
        for (int k = 0; k < KT; ++k) {
            float a[4];
#pragma unroll
            for (int i = 0; i < 4; ++i) a[i] = sA[r0 + i][k];
            float e[8];
            *(float4*)&e[0] = *(float4*)&sE[k][c0];
            *(float4*)&e[4] = *(float4*)&sE[k][c0 + 4];
            FMA_TILE(acc, a, e)
        }
        __syncthreads();
    }

    float* dst = g_pA[split];
#pragma unroll
    for (int i = 0; i < 4; ++i) {
        int rr = rb + r0 + i;
        if (rr < nF) {
            *(float4*)(dst + (size_t)rr * D + c0)     = *(float4*)&acc[i][0];
            *(float4*)(dst + (size_t)rr * D + c0 + 4) = *(float4*)&acc[i][4];
        }
    }
}

// -------- 6. Pass B: unflagged needed rows x flagged cols (gathered SGEMM, split-K) --------
__global__ void __launch_bounds__(128) k_passB(const float* __restrict__ adj) {
    int nF = g_cF, nU = g_cU;
    int rb = blockIdx.x * MT;
    if (rb >= nU) return;
    int split = blockIdx.y;
    int totTiles = (nF + KT - 1) / KT;
    int per = (totTiles + SPLITB - 1) / SPLITB;
    int t0 = split * per;
    int t1 = t0 + per; if (t1 > totTiles) t1 = totTiles;

    __shared__ float sA[MT][KT + 4];
    __shared__ float sE[KT][68];
    __shared__ const float* sRow[MT];

    int tid = threadIdx.x;
    if (tid < MT) {
        int rr = rb + tid; if (rr >= nU) rr = nU - 1;
        sRow[tid] = adj + (size_t)g_listU[rr] * NTOT;
    }
    __syncthreads();

    float acc[4][8];
#pragma unroll
    for (int i = 0; i < 4; ++i)
#pragma unroll
        for (int j = 0; j < 8; ++j) acc[i][j] = 0.f;

    int ty = tid >> 3, tx = tid & 7;
    int r0 = ty * 4, c0 = tx * 8;

    for (int t = t0; t < t1; ++t) {
        int g0 = t * KT;
        // stage adjacency tile: scattered scalar gathers, one warp per row,
        // ascending columns within warp for sector locality
#pragma unroll
        for (int j = 0; j < 16; ++j) {
            int idx = tid + j * 128;
            int row = idx >> 5, tt = idx & 31;
            int gt = g0 + tt;
            float v = 0.f;
            if (gt < nF) v = sRow[row][g_listF[gt]];
            sA[row][tt] = v;
        }
        // stage compact egoF (zero-padded; coalesced float4)
#pragma unroll
        for (int j = 0; j < 4; ++j) {
            int idx = tid + j * 128;
            int k = idx >> 4, dseg = idx & 15;
            float4 v = *(const float4*)(g_egoF + (size_t)(g0 + k) * D + dseg * 4);
            *(float4*)&sE[k][dseg * 4] = v;
        }
        __syncthreads();
#pragma unroll 8
        for (int k = 0; k < KT; ++k) {
            float a[4];
#pragma unroll
            for (int i = 0; i < 4; ++i) a[i] = sA[r0 + i][k];
            float e[8];
            *(float4*)&e[0] = *(float4*)&sE[k][c0];
            *(float4*)&e[4] = *(float4*)&sE[k][c0 + 4];
            FMA_TILE(acc, a, e)
        }
        __syncthreads();
    }

    float* dst = g_pB[split];
#pragma unroll
    for (int i = 0; i < 4; ++i) {
        int rr = rb + r0 + i;
        if (rr < nU) {
            *(float4*)(dst + (size_t)rr * D + c0)     = *(float4*)&acc[i][0];
            *(float4*)(dst + (size_t)rr * D + c0 + 4) = *(float4*)&acc[i][4];
        }
    }
}

// -------- 7. gather + deterministic split-K reduction --------
__global__ void k_gather(const int* __restrict__ users,
                         const int* __restrict__ pos,
                         const int* __restrict__ neg,
                         float* __restrict__ out) {
    int t = blockIdx.x * 256 + threadIdx.x;   // t < 12288 * 64
    int q = t >> 6, d = t & 63;
    int r;
    if (q < BATCH)            r = users[q];
    else if (q < 2 * BATCH)   r = N_USER + pos[q - BATCH];
    else                      r = N_USER + neg[q - 2 * BATCH];

    int p = g_pos[r];
    float s = 0.f;
    if (p < MAXF_PAD) {
#pragma unroll
        for (int k = 0; k < SPLITA; ++k) s += g_pA[k][(size_t)p * D + d];
    } else {
        int pu = p - MAXF_PAD;
#pragma unroll
        for (int k = 0; k < SPLITB; ++k) s += g_pB[k][(size_t)pu * D + d];
    }
    out[t] = 0.25f * (g_ego[(size_t)r * D + d] + 3.0f * s);
}

extern "C" void kernel_launch(void* const* d_in, const int* in_sizes, int n_in,
                              void* d_out, int out_size) {
    const float* adj   = (const float*)d_in[0];
    const float* ue    = (const float*)d_in[1];
    const float* ie    = (const float*)d_in[2];
    const int*   users = (const int*)d_in[3];
    const int*   pos   = (const int*)d_in[4];
    const int*   neg   = (const int*)d_in[5];
    float*       out   = (float*)d_out;

    k_init<<<NTOT, D>>>(ue, ie);
    k_scatter<<<(NNEG + 255) / 256, 256>>>(users, pos, neg);
    k_compact<<<1, 1024>>>();
    k_prep<<<MAXU, D>>>();
    dim3 gA((MAXF + MT - 1) / MT, SPLITA);
    k_passA<<<gA, 128>>>(adj);
    dim3 gB(MAXU / MT, SPLITB);
    k_passB<<<gB, 128>>>(adj);
    k_gather<<<(6 * BATCH * D) / 256, 256>>>(users, pos, neg, out);
}

// round 5
// speedup vs baseline: 1.5171x; 1.2536x over previous
#include <cuda_runtime.h>
#include <cuda_bf16.h>
#include <cstdint>

#define N_USER   6144
#define NTOT     12288
#define D        64
#define BATCH    2048
#define NNEG     8192
#define MAXF     2049
#define MAXU     10240
#define UBASE    2176                 // 17 F-tiles * 128
#define SLOTS    (UBASE + MAXU)
#define KT       64                   // K per B tile
#define NSPLIT   2
#define KSPL     (NTOT / NSPLIT)      // 6144
#define NKT      (KSPL / KT)          // 96
#define NTILES   97                   // 17 F + 80 U upper bound
#define BSTRIDE  72                   // padded bf16 row stride for B smem

// -------- device scratch --------
__device__ float g_ego[NTOT * D];
__device__ __nv_bfloat16 g_eThi[(size_t)D * NTOT], g_eTlo[(size_t)D * NTOT];
__device__ __nv_bfloat16 g_eMhi[(size_t)D * NTOT], g_eMlo[(size_t)D * NTOT];
__device__ int g_flag[NTOT], g_needed[NTOT];
__device__ int g_listF[MAXF], g_listU[MAXU], g_pos[NTOT];
__device__ int g_cF, g_cU;
__device__ float g_part[NSPLIT][(size_t)SLOTS * D];

__device__ __forceinline__ uint32_t smem_u32(const void* p) {
    uint32_t a;
    asm("{ .reg .u64 t; cvta.to.shared.u64 t, %1; cvt.u32.u64 %0, t; }" : "=r"(a) : "l"(p));
    return a;
}
__device__ __forceinline__ void cp16(uint32_t dst, const void* src) {
    asm volatile("cp.async.ca.shared.global [%0], [%1], 16;" :: "r"(dst), "l"(src));
}
#define CP_COMMIT() asm volatile("cp.async.commit_group;" ::: "memory")
#define CP_WAIT(n)  asm volatile("cp.async.wait_group %0;" :: "n"(n) : "memory")

// non-trans: lane l gets k-adjacent pair from row l/4 -> exact B fragment
__device__ __forceinline__ void ldmx4(uint32_t* r, uint32_t addr) {
    asm volatile("ldmatrix.sync.aligned.m8n8.x4.shared.b16 {%0,%1,%2,%3}, [%4];"
                 : "=r"(r[0]), "=r"(r[1]), "=r"(r[2]), "=r"(r[3]) : "r"(addr));
}
__device__ __forceinline__ void mma16816(float* c, const uint32_t* a, const uint32_t* b) {
    asm volatile("mma.sync.aligned.m16n8k16.row.col.f32.bf16.bf16.f32 "
                 "{%0,%1,%2,%3},{%4,%5,%6,%7},{%8,%9},{%0,%1,%2,%3};"
                 : "+f"(c[0]), "+f"(c[1]), "+f"(c[2]), "+f"(c[3])
                 : "r"(a[0]), "r"(a[1]), "r"(a[2]), "r"(a[3]), "r"(b[0]), "r"(b[1]));
}

// -------- 1. init --------
__global__ void k_init(const float* __restrict__ ue, const float* __restrict__ ie) {
    int r = blockIdx.x, d = threadIdx.x;
    g_ego[r * D + d] = (r < N_USER) ? ue[r * D + d] : ie[(r - N_USER) * D + d];
    if (d == 0) { g_flag[r] = 0; g_needed[r] = 0; }
}

// -------- 2. scatter --------
__global__ void k_scatter(const int* __restrict__ users, const int* __restrict__ pos,
                          const int* __restrict__ neg) {
    int t = blockIdx.x * blockDim.x + threadIdx.x;
    if (t == 0) g_flag[users[0]] = 1;
    if (t < BATCH) {
        int rp = N_USER + pos[t];
        g_flag[rp] = 1; g_needed[rp] = 1;
        g_needed[users[t]] = 1;
    }
    if (t < NNEG) g_needed[N_USER + neg[t]] = 1;
}

// -------- 3. deterministic compaction --------
__global__ void k_compact() {
    __shared__ int warpF[32], warpU[32];
    __shared__ int baseF, baseU;
    int tid = threadIdx.x, lane = tid & 31, wid = tid >> 5;
    if (tid == 0) { baseF = 0; baseU = 0; }
    __syncthreads();
    for (int base = 0; base < NTOT; base += 1024) {
        int i = base + tid;
        int f = g_flag[i];
        int u = (!f) && g_needed[i];
        unsigned bf = __ballot_sync(0xFFFFFFFFu, f);
        unsigned bu = __ballot_sync(0xFFFFFFFFu, u);
        if (lane == 0) { warpF[wid] = __popc(bf); warpU[wid] = __popc(bu); }
        __syncthreads();
        int offF = baseF, offU = baseU;
        for (int k = 0; k < wid; ++k) { offF += warpF[k]; offU += warpU[k]; }
        if (f) g_listF[offF + __popc(bf & ((1u << lane) - 1u))] = i;
        if (u) g_listU[offU + __popc(bu & ((1u << lane) - 1u))] = i;
        __syncthreads();
        if (tid == 0)
            for (int k = 0; k < 32; ++k) { baseF += warpF[k]; baseU += warpU[k]; }
        __syncthreads();
    }
    if (tid == 0) { g_cF = baseF; g_cU = baseU; }
}

// -------- 4. slot map --------
__global__ void k_prep() {
    int j = blockIdx.x * 256 + threadIdx.x;
    if (j < g_cF) g_pos[g_listF[j]] = j;
    if (j < g_cU) g_pos[g_listU[j]] = UBASE + j;
}

// -------- 5. transpose ego -> bf16 hi/lo (plus flag-masked copies) --------
__global__ void k_prepT() {
    int k = blockIdx.x * 256 + threadIdx.x;
    int n = blockIdx.y;
    float x = g_ego[(size_t)k * D + n];
    __nv_bfloat16 h = __float2bfloat16(x);
    float hf = __bfloat162float(h);
    __nv_bfloat16 l = __float2bfloat16(x - hf);
    size_t o = (size_t)n * NTOT + k;
    g_eThi[o] = h; g_eTlo[o] = l;
    bool f = g_flag[k] != 0;
    __nv_bfloat16 z = __float2bfloat16(0.f);
    g_eMhi[o] = f ? h : z;
    g_eMlo[o] = f ? l : z;
}

// -------- 6. main GEMM: mma.sync bf16 hi/lo, A direct from gmem, B via cp.async --------
__global__ void __launch_bounds__(256) k_main(const float* __restrict__ adj) {
    __shared__ __nv_bfloat16 sBh[2][64 * BSTRIDE];
    __shared__ __nv_bfloat16 sBl[2][64 * BSTRIDE];
    __shared__ const float* sRow[128];

    int tid = threadIdx.x, wid = tid >> 5, lane = tid & 31;
    int cF = g_cF, cU = g_cU;
    int nTF = (cF + 127) >> 7;
    int t = blockIdx.x, split = blockIdx.y;

    int slotBase, j0, cnt;
    const int* list;
    const __nv_bfloat16 *bh, *bl;
    if (t < nTF) {
        j0 = t * 128; slotBase = j0; list = g_listF; cnt = cF; bh = g_eThi; bl = g_eTlo;
    } else {
        int u = t - nTF;
        if (u * 128 >= cU) return;
        j0 = u * 128; slotBase = UBASE + j0; list = g_listU; cnt = cU; bh = g_eMhi; bl = g_eMlo;
    }
    size_t kbase = (size_t)split * KSPL;

    if (tid < 128) {
        int j = j0 + tid; if (j >= cnt) j = cnt - 1;
        sRow[tid] = adj + (size_t)list[j] * NTOT + kbase;
    }
    __syncthreads();

    // per-lane A row pointers (constant across tiles)
    const float* pr0 = sRow[wid * 16 + (lane >> 2)];
    const float* pr1 = sRow[wid * 16 + 8 + (lane >> 2)];
    int ac = (lane & 3) * 2;   // A k sub-offset

    const __nv_bfloat16* bhp = bh + kbase;
    const __nv_bfloat16* blp = bl + kbase;

    // B staging: 512 16B-chunks per (hi|lo) tile; thread does 2 hi + 2 lo
    int c_n0 = (tid * 2) >> 3, c_c0 = (tid * 2) & 7;          // chunk ids tid*2, tid*2+1
    int c_n1 = (tid * 2 + 1) >> 3, c_c1 = (tid * 2 + 1) & 7;
    uint32_t sbh0 = smem_u32(&sBh[0][0]), sbl0 = smem_u32(&sBl[0][0]);
    uint32_t dsth0 = (uint32_t)((c_n0 * BSTRIDE + c_c0 * 8) * 2);
    uint32_t dsth1 = (uint32_t)((c_n1 * BSTRIDE + c_c1 * 8) * 2);
    size_t srco0 = (size_t)c_n0 * NTOT + c_c0 * 8;
    size_t srco1 = (size_t)c_n1 * NTOT + c_c1 * 8;
    const uint32_t BUFB = (uint32_t)(64 * BSTRIDE * 2);

    // ldmatrix lane addressing (non-trans; B stored [n][k], k contiguous)
    int lrow = (lane & 7) + ((lane >> 4) << 3);    // n within 16-block
    int lk = ((lane >> 3) & 1) * 8;                // k half
    uint32_t lmoff = (uint32_t)((lrow * BSTRIDE + lk) * 2);

    float acc[8][4];
#pragma unroll
    for (int nb = 0; nb < 8; ++nb)
#pragma unroll
        for (int i = 0; i < 4; ++i) acc[nb][i] = 0.f;

    // prologue: stage B tile 0 into buf 0
    {
        cp16(sbh0 + dsth0, bhp + srco0);
        cp16(sbh0 + dsth1, bhp + srco1);
        cp16(sbl0 + dsth0, blp + srco0);
        cp16(sbl0 + dsth1, blp + srco1);
        CP_COMMIT();
    }

    for (int kt = 0; kt < NKT; ++kt) {
        int buf = kt & 1;
        if (kt + 1 < NKT) {
            int nb2 = (kt + 1) & 1;
            size_t ko = (size_t)(kt + 1) * KT;
            cp16(sbh0 + nb2 * BUFB + dsth0, bhp + srco0 + ko);
            cp16(sbh0 + nb2 * BUFB + dsth1, bhp + srco1 + ko);
            cp16(sbl0 + nb2 * BUFB + dsth0, blp + srco0 + ko);
            cp16(sbl0 + nb2 * BUFB + dsth1, blp + srco1 + ko);
            CP_COMMIT();
            CP_WAIT(1);
        } else {
            CP_WAIT(0);
        }
        __syncthreads();

        int k0 = kt * KT;
        uint32_t bhbase = sbh0 + buf * BUFB + lmoff;
        uint32_t blbase = sbl0 + buf * BUFB + lmoff;

#pragma unroll
        for (int ks = 0; ks < 4; ++ks) {
            int kk = k0 + ks * 16 + ac;
            // A fragments direct from gmem, split hi/lo in regs
            float2 x0 = *(const float2*)(pr0 + kk);
            float2 x1 = *(const float2*)(pr1 + kk);
            float2 x2 = *(const float2*)(pr0 + kk + 8);
            float2 x3 = *(const float2*)(pr1 + kk + 8);
            uint32_t ah[4], al[4];
            {
                __nv_bfloat162 h; float2 hf; __nv_bfloat162 l;
                h = __float22bfloat162_rn(x0); hf = __bfloat1622float2(h);
                l = __float22bfloat162_rn(make_float2(x0.x - hf.x, x0.y - hf.y));
                ah[0] = *(uint32_t*)&h; al[0] = *(uint32_t*)&l;
                h = __float22bfloat162_rn(x1); hf = __bfloat1622float2(h);
                l = __float22bfloat162_rn(make_float2(x1.x - hf.x, x1.y - hf.y));
                ah[1] = *(uint32_t*)&h; al[1] = *(uint32_t*)&l;
                h = __float22bfloat162_rn(x2); hf = __bfloat1622float2(h);
                l = __float22bfloat162_rn(make_float2(x2.x - hf.x, x2.y - hf.y));
                ah[2] = *(uint32_t*)&h; al[2] = *(uint32_t*)&l;
                h = __float22bfloat162_rn(x3); hf = __bfloat1622float2(h);
                l = __float22bfloat162_rn(make_float2(x3.x - hf.x, x3.y - hf.y));
                ah[3] = *(uint32_t*)&h; al[3] = *(uint32_t*)&l;
            }
            uint32_t bhf[8][2], blf[8][2];
#pragma unroll
            for (int p = 0; p < 4; ++p) {
                uint32_t r[4];
                uint32_t o = (uint32_t)(p * 16 * BSTRIDE * 2 + ks * 32);
                ldmx4(r, bhbase + o);
                bhf[p*2][0] = r[0]; bhf[p*2][1] = r[1];
                bhf[p*2+1][0] = r[2]; bhf[p*2+1][1] = r[3];
                ldmx4(r, blbase + o);
                blf[p*2][0] = r[0]; blf[p*2][1] = r[1];
                blf[p*2+1][0] = r[2]; blf[p*2+1][1] = r[3];
            }
#pragma unroll
            for (int nb = 0; nb < 8; ++nb) {
                mma16816(acc[nb], ah, bhf[nb]);
                mma16816(acc[nb], ah, blf[nb]);
                mma16816(acc[nb], al, bhf[nb]);
            }
        }
        __syncthreads();
    }

    // epilogue: c0,c1 -> row lane/4 ; c2,c3 -> row lane/4+8 ; cols nb*8+(lane&3)*2
    float* dst = g_part[split];
    int r0 = slotBase + wid * 16 + (lane >> 2);
#pragma unroll
    for (int nb = 0; nb < 8; ++nb) {
        int col = nb * 8 + (lane & 3) * 2;
        *(float2*)(dst + (size_t)r0 * D + col)       = make_float2(acc[nb][0], acc[nb][1]);
        *(float2*)(dst + (size_t)(r0 + 8) * D + col) = make_float2(acc[nb][2], acc[nb][3]);
    }
}

// -------- 7. gather + deterministic split reduction --------
__global__ void k_gather(const int* __restrict__ users, const int* __restrict__ pos,
                         const int* __restrict__ neg, float* __restrict__ out) {
    int t = blockIdx.x * 256 + threadIdx.x;
    int q = t >> 6, d = t & 63;
    int r;
    if (q < BATCH)          r = users[q];
    else if (q < 2 * BATCH) r = N_USER + pos[q - BATCH];
    else                    r = N_USER + neg[q - 2 * BATCH];
    int p = g_pos[r];
    float s = g_part[0][(size_t)p * D + d] + g_part[1][(size_t)p * D + d];
    out[t] = 0.25f * (g_ego[(size_t)r * D + d] + 3.0f * s);
}

extern "C" void kernel_launch(void* const* d_in, const int* in_sizes, int n_in,
                              void* d_out, int out_size) {
    const float* adj   = (const float*)d_in[0];
    const float* ue    = (const float*)d_in[1];
    const float* ie    = (const float*)d_in[2];
    const int*   users = (const int*)d_in[3];
    const int*   pos   = (const int*)d_in[4];
    const int*   neg   = (const int*)d_in[5];
    float*       out   = (float*)d_out;

    k_init<<<NTOT, D>>>(ue, ie);
    k_scatter<<<(NNEG + 255) / 256, 256>>>(users, pos, neg);
    k_compact<<<1, 1024>>>();
    k_prep<<<(MAXU + 255) / 256, 256>>>();
    dim3 gT(NTOT / 256, D);
    k_prepT<<<gT, 256>>>();
    dim3 gM(NTILES, NSPLIT);
    k_main<<<gM, 256>>>(adj);
    k_gather<<<(6 * BATCH * D) / 256, 256>>>(users, pos, neg, out);
}

// round 6
// speedup vs baseline: 2.7875x; 1.8373x over previous
#include <cuda_runtime.h>
#include <cuda_bf16.h>
#include <cstdint>

#define N_USER   6144
#define NTOT     12288
#define D        64
#define BATCH    2048
#define NNEG     8192
#define MAXF     2049
#define MAXU     10240
#define UBASE    2176                 // 17 F-tiles * 128
#define SLOTS    (UBASE + MAXU)
#define KT       64                   // K per B tile
#define NSPLIT   4
#define KSPL_F   (NTOT / NSPLIT)      // 3072
#define KSPL_U   (N_USER / NSPLIT)    // 1536 (upper half only)
#define NTILES   97
#define BSTRIDE  72                   // padded bf16 row stride for B smem

// -------- device scratch --------
__device__ float g_ego[NTOT * D];
__device__ __nv_bfloat16 g_eThi[(size_t)D * NTOT], g_eTlo[(size_t)D * NTOT];
__device__ __nv_bfloat16 g_eMhi[(size_t)D * NTOT], g_eMlo[(size_t)D * NTOT];
__device__ int g_flag[NTOT], g_needed[NTOT];
__device__ int g_listF[MAXF], g_listU[MAXU], g_pos[NTOT];
__device__ int g_cF, g_cU;
__device__ float g_part[NSPLIT][(size_t)SLOTS * D];

__device__ __forceinline__ uint32_t smem_u32(const void* p) {
    uint32_t a;
    asm("{ .reg .u64 t; cvta.to.shared.u64 t, %1; cvt.u32.u64 %0, t; }" : "=r"(a) : "l"(p));
    return a;
}
__device__ __forceinline__ void cp16(uint32_t dst, const void* src) {
    asm volatile("cp.async.ca.shared.global [%0], [%1], 16;" :: "r"(dst), "l"(src));
}
#define CP_COMMIT() asm volatile("cp.async.commit_group;" ::: "memory")
#define CP_WAIT(n)  asm volatile("cp.async.wait_group %0;" :: "n"(n) : "memory")

__device__ __forceinline__ void ldmx4(uint32_t* r, uint32_t addr) {
    asm volatile("ldmatrix.sync.aligned.m8n8.x4.shared.b16 {%0,%1,%2,%3}, [%4];"
                 : "=r"(r[0]), "=r"(r[1]), "=r"(r[2]), "=r"(r[3]) : "r"(addr));
}
__device__ __forceinline__ void mma16816(float* c, const uint32_t* a, const uint32_t* b) {
    asm volatile("mma.sync.aligned.m16n8k16.row.col.f32.bf16.bf16.f32 "
                 "{%0,%1,%2,%3},{%4,%5,%6,%7},{%8,%9},{%0,%1,%2,%3};"
                 : "+f"(c[0]), "+f"(c[1]), "+f"(c[2]), "+f"(c[3])
                 : "r"(a[0]), "r"(a[1]), "r"(a[2]), "r"(a[3]), "r"(b[0]), "r"(b[1]));
}

// -------- 1. init --------
__global__ void k_init(const float* __restrict__ ue, const float* __restrict__ ie) {
    int r = blockIdx.x, d = threadIdx.x;
    g_ego[r * D + d] = (r < N_USER) ? ue[r * D + d] : ie[(r - N_USER) * D + d];
    if (d == 0) { g_flag[r] = 0; g_needed[r] = 0; }
}

// -------- 2. scatter --------
__global__ void k_scatter(const int* __restrict__ users, const int* __restrict__ pos,
                          const int* __restrict__ neg) {
    int t = blockIdx.x * blockDim.x + threadIdx.x;
    if (t == 0) g_flag[users[0]] = 1;
    if (t < BATCH) {
        int rp = N_USER + pos[t];
        g_flag[rp] = 1; g_needed[rp] = 1;
        g_needed[users[t]] = 1;
    }
    if (t < NNEG) g_needed[N_USER + neg[t]] = 1;
}

// -------- 3. deterministic compaction --------
__global__ void k_compact() {
    __shared__ int warpF[32], warpU[32];
    __shared__ int baseF, baseU;
    int tid = threadIdx.x, lane = tid & 31, wid = tid >> 5;
    if (tid == 0) { baseF = 0; baseU = 0; }
    __syncthreads();
    for (int base = 0; base < NTOT; base += 1024) {
        int i = base + tid;
        int f = g_flag[i];
        int u = (!f) && g_needed[i];
        unsigned bf = __ballot_sync(0xFFFFFFFFu, f);
        unsigned bu = __ballot_sync(0xFFFFFFFFu, u);
        if (lane == 0) { warpF[wid] = __popc(bf); warpU[wid] = __popc(bu); }
        __syncthreads();
        int offF = baseF, offU = baseU;
        for (int k = 0; k < wid; ++k) { offF += warpF[k]; offU += warpU[k]; }
        if (f) g_listF[offF + __popc(bf & ((1u << lane) - 1u))] = i;
        if (u) g_listU[offU + __popc(bu & ((1u << lane) - 1u))] = i;
        __syncthreads();
        if (tid == 0)
            for (int k = 0; k < 32; ++k) { baseF += warpF[k]; baseU += warpU[k]; }
        __syncthreads();
    }
    if (tid == 0) { g_cF = baseF; g_cU = baseU; }
}

// -------- 4. slot map --------
__global__ void k_prep() {
    int j = blockIdx.x * 256 + threadIdx.x;
    if (j < g_cF) g_pos[g_listF[j]] = j;
    if (j < g_cU) g_pos[g_listU[j]] = UBASE + j;
}

// -------- 5. tiled transpose: ego -> bf16 hi/lo T (masked copies upper half only) --------
__global__ void k_prepT() {
    __shared__ float tile[64][65];
    __shared__ int sflag[64];
    int k0 = blockIdx.x * 64;
    int tid = threadIdx.x;
    if (tid < 64) sflag[tid] = g_flag[k0 + tid];
#pragma unroll
    for (int i = 0; i < 16; ++i) {
        int e = tid + i * 256;
        int k = e >> 6, n = e & 63;
        tile[k][n] = g_ego[(size_t)(k0 + k) * D + n];
    }
    __syncthreads();
    bool upper = (k0 >= N_USER);
#pragma unroll
    for (int i = 0; i < 16; ++i) {
        int e = tid + i * 256;
        int n = e >> 6, kk = e & 63;
        float x = tile[kk][n];
        __nv_bfloat16 h = __float2bfloat16(x);
        float hf = __bfloat162float(h);
        __nv_bfloat16 l = __float2bfloat16(x - hf);
        size_t o = (size_t)n * NTOT + k0 + kk;
        g_eThi[o] = h; g_eTlo[o] = l;
        if (upper) {
            bool f = sflag[kk] != 0;
            __nv_bfloat16 z = __float2bfloat16(0.f);
            g_eMhi[o] = f ? h : z;
            g_eMlo[o] = f ? l : z;
        }
    }
}

// -------- 6. main GEMM --------
__global__ void __launch_bounds__(256, 2) k_main(const float* __restrict__ adj) {
    __shared__ __nv_bfloat16 sBh[2][64 * BSTRIDE];
    __shared__ __nv_bfloat16 sBl[2][64 * BSTRIDE];
    __shared__ const float* sRow[128];

    int tid = threadIdx.x, wid = tid >> 5, lane = tid & 31;
    int cF = g_cF, cU = g_cU;
    int nTF = (cF + 127) >> 7;
    int t = blockIdx.x, split = blockIdx.y;

    int slotBase, j0, cnt, nkt;
    size_t kbase;
    const int* list;
    const __nv_bfloat16 *bh, *bl;
    if (t < nTF) {
        j0 = t * 128; slotBase = j0; list = g_listF; cnt = cF;
        bh = g_eThi; bl = g_eTlo;
        kbase = (size_t)split * KSPL_F; nkt = KSPL_F / KT;     // 48
    } else {
        int u = t - nTF;
        if (u * 128 >= cU) return;
        j0 = u * 128; slotBase = UBASE + j0; list = g_listU; cnt = cU;
        bh = g_eMhi; bl = g_eMlo;
        kbase = (size_t)N_USER + (size_t)split * KSPL_U; nkt = KSPL_U / KT;  // 24
    }

    if (tid < 128) {
        int j = j0 + tid; if (j >= cnt) j = cnt - 1;
        sRow[tid] = adj + (size_t)list[j] * NTOT + kbase;
    }
    __syncthreads();

    const float* pr0 = sRow[wid * 16 + (lane >> 2)];
    const float* pr1 = sRow[wid * 16 + 8 + (lane >> 2)];
    int ac = (lane & 3) * 2;

    const __nv_bfloat16* bhp = bh + kbase;
    const __nv_bfloat16* blp = bl + kbase;

    int c_n0 = (tid * 2) >> 3, c_c0 = (tid * 2) & 7;
    int c_n1 = (tid * 2 + 1) >> 3, c_c1 = (tid * 2 + 1) & 7;
    uint32_t sbh0 = smem_u32(&sBh[0][0]), sbl0 = smem_u32(&sBl[0][0]);
    uint32_t dsth0 = (uint32_t)((c_n0 * BSTRIDE + c_c0 * 8) * 2);
    uint32_t dsth1 = (uint32_t)((c_n1 * BSTRIDE + c_c1 * 8) * 2);
    size_t srco0 = (size_t)c_n0 * NTOT + c_c0 * 8;
    size_t srco1 = (size_t)c_n1 * NTOT + c_c1 * 8;
    const uint32_t BUFB = (uint32_t)(64 * BSTRIDE * 2);

    int lrow = (lane & 7) + ((lane >> 4) << 3);
    int lk = ((lane >> 3) & 1) * 8;
    uint32_t lmoff = (uint32_t)((lrow * BSTRIDE + lk) * 2);

    float acc[8][4];
#pragma unroll
    for (int nb = 0; nb < 8; ++nb)
#pragma unroll
        for (int i = 0; i < 4; ++i) acc[nb][i] = 0.f;

    cp16(sbh0 + dsth0, bhp + srco0);
    cp16(sbh0 + dsth1, bhp + srco1);
    cp16(sbl0 + dsth0, blp + srco0);
    cp16(sbl0 + dsth1, blp + srco1);
    CP_COMMIT();

    for (int kt = 0; kt < nkt; ++kt) {
        int buf = kt & 1;
        if (kt + 1 < nkt) {
            int nb2 = (kt + 1) & 1;
            size_t ko = (size_t)(kt + 1) * KT;
            cp16(sbh0 + nb2 * BUFB + dsth0, bhp + srco0 + ko);
            cp16(sbh0 + nb2 * BUFB + dsth1, bhp + srco1 + ko);
            cp16(sbl0 + nb2 * BUFB + dsth0, blp + srco0 + ko);
            cp16(sbl0 + nb2 * BUFB + dsth1, blp + srco1 + ko);
            CP_COMMIT();
            CP_WAIT(1);
        } else {
            CP_WAIT(0);
        }
        __syncthreads();

        int k0 = kt * KT;
        uint32_t bhbase = sbh0 + buf * BUFB + lmoff;
        uint32_t blbase = sbl0 + buf * BUFB + lmoff;

#pragma unroll
        for (int ks = 0; ks < 4; ++ks) {
            int kk = k0 + ks * 16 + ac;
            float2 x0 = *(const float2*)(pr0 + kk);
            float2 x1 = *(const float2*)(pr1 + kk);
            float2 x2 = *(const float2*)(pr0 + kk + 8);
            float2 x3 = *(const float2*)(pr1 + kk + 8);
            uint32_t ah[4], al[4];
            {
                __nv_bfloat162 h; float2 hf; __nv_bfloat162 l;
                h = __float22bfloat162_rn(x0); hf = __bfloat1622float2(h);
                l = __float22bfloat162_rn(make_float2(x0.x - hf.x, x0.y - hf.y));
                ah[0] = *(uint32_t*)&h; al[0] = *(uint32_t*)&l;
                h = __float22bfloat162_rn(x1); hf = __bfloat1622float2(h);
                l = __float22bfloat162_rn(make_float2(x1.x - hf.x, x1.y - hf.y));
                ah[1] = *(uint32_t*)&h; al[1] = *(uint32_t*)&l;
                h = __float22bfloat162_rn(x2); hf = __bfloat1622float2(h);
                l = __float22bfloat162_rn(make_float2(x2.x - hf.x, x2.y - hf.y));
                ah[2] = *(uint32_t*)&h; al[2] = *(uint32_t*)&l;
                h = __float22bfloat162_rn(x3); hf = __bfloat1622float2(h);
                l = __float22bfloat162_rn(make_float2(x3.x - hf.x, x3.y - hf.y));
                ah[3] = *(uint32_t*)&h; al[3] = *(uint32_t*)&l;
            }
            uint32_t bhf[8][2], blf[8][2];
#pragma unroll
            for (int p = 0; p < 4; ++p) {
                uint32_t r[4];
                uint32_t o = (uint32_t)(p * 16 * BSTRIDE * 2 + ks * 32);
                ldmx4(r, bhbase + o);
                bhf[p*2][0] = r[0]; bhf[p*2][1] = r[1];
                bhf[p*2+1][0] = r[2]; bhf[p*2+1][1] = r[3];
                ldmx4(r, blbase + o);
                blf[p*2][0] = r[0]; blf[p*2][1] = r[1];
                blf[p*2+1][0] = r[2]; blf[p*2+1][1] = r[3];
            }
#pragma unroll
            for (int nb = 0; nb < 8; ++nb) {
                mma16816(acc[nb], ah, bhf[nb]);
                mma16816(acc[nb], ah, blf[nb]);
                mma16816(acc[nb], al, bhf[nb]);
            }
        }
        __syncthreads();
    }

    float* dst = g_part[split];
    int r0 = slotBase + wid * 16 + (lane >> 2);
#pragma unroll
    for (int nb = 0; nb < 8; ++nb) {
        int col = nb * 8 + (lane & 3) * 2;
        *(float2*)(dst + (size_t)r0 * D + col)       = make_float2(acc[nb][0], acc[nb][1]);
        *(float2*)(dst + (size_t)(r0 + 8) * D + col) = make_float2(acc[nb][2], acc[nb][3]);
    }
}

// -------- 7. gather + deterministic reduction + rank-1 user column for U rows --------
__global__ void k_gather(const float* __restrict__ adj,
                         const int* __restrict__ users, const int* __restrict__ pos,
                         const int* __restrict__ neg, float* __restrict__ out) {
    int t = blockIdx.x * 256 + threadIdx.x;
    int q = t >> 6, d = t & 63;
    int r;
    if (q < BATCH)          r = users[q];
    else if (q < 2 * BATCH) r = N_USER + pos[q - BATCH];
    else                    r = N_USER + neg[q - 2 * BATCH];
    int p = g_pos[r];
    float s = g_part[0][(size_t)p * D + d] + g_part[1][(size_t)p * D + d]
            + g_part[2][(size_t)p * D + d] + g_part[3][(size_t)p * D + d];
    if (p >= UBASE) {
        int u0 = users[0];
        s += adj[(size_t)r * NTOT + u0] * g_ego[(size_t)u0 * D + d];
    }
    out[t] = 0.25f * (g_ego[(size_t)r * D + d] + 3.0f * s);
}

extern "C" void kernel_launch(void* const* d_in, const int* in_sizes, int n_in,
                              void* d_out, int out_size) {
    const float* adj   = (const float*)d_in[0];
    const float* ue    = (const float*)d_in[1];
    const float* ie    = (const float*)d_in[2];
    const int*   users = (const int*)d_in[3];
    const int*   pos   = (const int*)d_in[4];
    const int*   neg   = (const int*)d_in[5];
    float*       out   = (float*)d_out;

    k_init<<<NTOT, D>>>(ue, ie);
    k_scatter<<<(NNEG + 255) / 256, 256>>>(users, pos, neg);
    k_compact<<<1, 1024>>>();
    k_prep<<<(MAXU + 255) / 256, 256>>>();
    k_prepT<<<NTOT / 64, 256>>>();
    dim3 gM(NTILES, NSPLIT);
    k_main<<<gM, 256>>>(adj);
    k_gather<<<(6 * BATCH * D) / 256, 256>>>(adj, users, pos, neg, out);
}